// round 3
// baseline (speedup 1.0000x reference)
#include <cuda_runtime.h>
#include <cstdint>

// Problem-size maxima (fixed by the reference generator).
static constexpr int NMAX = 1000000;
static constexpr int GMAX = 1000;

// Node state + aggregation buffer: 2 float4 per node (row stride 32B, only
// first 6 floats meaningful). float4 type guarantees 16B alignment for the
// vectorized loads and red.global atomics.
__device__ float4 g_h  [(size_t)NMAX * 2];
__device__ float4 g_agg[(size_t)NMAX * 2];
__device__ float  g_gsum[GMAX];
__device__ float  g_gcnt[GMAX];

// ---------------------------------------------------------------------------
// Init: h <- x (padded), agg <- 0, pool accumulators <- 0.
// ---------------------------------------------------------------------------
__global__ __launch_bounds__(256) void init_kernel(const float* __restrict__ x,
                                                   int N, int G) {
    int i = blockIdx.x * 256 + threadIdx.x;
    if (i < N) {
        const float2* xp = reinterpret_cast<const float2*>(x + (size_t)i * 6);
        float2 a = __ldcs(xp + 0);
        float2 b = __ldcs(xp + 1);
        float2 c = __ldcs(xp + 2);
        g_h[(size_t)i * 2 + 0] = make_float4(a.x, a.y, b.x, b.y);
        g_h[(size_t)i * 2 + 1] = make_float4(c.x, c.y, 0.f, 0.f);
        g_agg[(size_t)i * 2 + 0] = make_float4(0.f, 0.f, 0.f, 0.f);
        g_agg[(size_t)i * 2 + 1] = make_float4(0.f, 0.f, 0.f, 0.f);
    }
    if (i < G) { g_gsum[i] = 0.f; g_gcnt[i] = 0.f; }
}

// ---------------------------------------------------------------------------
// Edge pass: m = relu(h[src] + e), agg[dst] += m  (vectorized red.global).
// edge_index (int32!) / edge_attr streamed with .cs so the ~384MB/layer
// stream doesn't evict the 64MB h/agg working set from L2.
// ---------------------------------------------------------------------------
__global__ __launch_bounds__(256) void edge_kernel(const int* __restrict__ ei,
                                                   const float* __restrict__ ea,
                                                   int E) {
    int e = blockIdx.x * 256 + threadIdx.x;
    if (e >= E) return;
    int s = __ldcs(ei + e);
    int d = __ldcs(ei + (size_t)E + e);

    float4 h4 = __ldg(&g_h[(size_t)s * 2 + 0]);
    float4 h2 = __ldg(&g_h[(size_t)s * 2 + 1]);

    const float2* ep = reinterpret_cast<const float2*>(ea + (size_t)e * 6);
    float2 e0 = __ldcs(ep + 0);
    float2 e1 = __ldcs(ep + 1);
    float2 e2 = __ldcs(ep + 2);

    float m0 = fmaxf(h4.x + e0.x, 0.f);
    float m1 = fmaxf(h4.y + e0.y, 0.f);
    float m2 = fmaxf(h4.z + e1.x, 0.f);
    float m3 = fmaxf(h4.w + e1.y, 0.f);
    float m4 = fmaxf(h2.x + e2.x, 0.f);
    float m5 = fmaxf(h2.y + e2.y, 0.f);

    unsigned long long ap =
        (unsigned long long)__cvta_generic_to_global(&g_agg[(size_t)d * 2]);
    asm volatile("red.global.add.v4.f32 [%0], {%1,%2,%3,%4};"
                 :: "l"(ap), "f"(m0), "f"(m1), "f"(m2), "f"(m3) : "memory");
    asm volatile("red.global.add.v2.f32 [%0], {%1,%2};"
                 :: "l"(ap + 16), "f"(m4), "f"(m5) : "memory");
}

// ---------------------------------------------------------------------------
// Node update: h <- relu((h + agg) @ W + b); agg <- 0 (for next layer).
// ---------------------------------------------------------------------------
__global__ __launch_bounds__(256) void node_kernel(const float* __restrict__ W,
                                                   const float* __restrict__ b,
                                                   int N) {
    __shared__ float sW[36];
    __shared__ float sb[6];
    if (threadIdx.x < 36) sW[threadIdx.x] = W[threadIdx.x];
    if (threadIdx.x < 6)  sb[threadIdx.x] = b[threadIdx.x];
    __syncthreads();

    int i = blockIdx.x * 256 + threadIdx.x;
    if (i >= N) return;

    float4 h4 = g_h[(size_t)i * 2 + 0];
    float4 h2 = g_h[(size_t)i * 2 + 1];
    float4 a4 = g_agg[(size_t)i * 2 + 0];
    float4 a2 = g_agg[(size_t)i * 2 + 1];

    float t[6] = {h4.x + a4.x, h4.y + a4.y, h4.z + a4.z,
                  h4.w + a4.w, h2.x + a2.x, h2.y + a2.y};
    float y[6];
#pragma unroll
    for (int j = 0; j < 6; j++) {
        float acc = sb[j];
#pragma unroll
        for (int k = 0; k < 6; k++) acc = fmaf(t[k], sW[k * 6 + j], acc);
        y[j] = fmaxf(acc, 0.f);
    }

    g_h[(size_t)i * 2 + 0] = make_float4(y[0], y[1], y[2], y[3]);
    g_h[(size_t)i * 2 + 1] = make_float4(y[4], y[5], 0.f, 0.f);
    g_agg[(size_t)i * 2 + 0] = make_float4(0.f, 0.f, 0.f, 0.f);
    g_agg[(size_t)i * 2 + 1] = make_float4(0.f, 0.f, 0.f, 0.f);
}

// ---------------------------------------------------------------------------
// Layer-3 node update fused with pooling head:
//   y = (h + agg) @ W3 + b3 (no relu);  s = y . Wl
//   pooled@Wl = (sum_i s_i)/cnt, so accumulate (s, 1) per graph.
// batch (int32, sorted) -> warp-segmented reduction, ~1 atomic per run.
// ---------------------------------------------------------------------------
__global__ __launch_bounds__(256) void node3_kernel(const float* __restrict__ W,
                                                    const float* __restrict__ b,
                                                    const float* __restrict__ Wl,
                                                    const int* __restrict__ batch,
                                                    int N) {
    __shared__ float sW[36];
    __shared__ float sb[6];
    __shared__ float sWl[6];
    if (threadIdx.x < 36) sW[threadIdx.x] = W[threadIdx.x];
    if (threadIdx.x < 6) { sb[threadIdx.x] = b[threadIdx.x]; sWl[threadIdx.x] = Wl[threadIdx.x]; }
    __syncthreads();

    int i = blockIdx.x * 256 + threadIdx.x;
    float s = 0.f, c = 0.f;
    int g = -1;
    if (i < N) {
        float4 h4 = g_h[(size_t)i * 2 + 0];
        float4 h2 = g_h[(size_t)i * 2 + 1];
        float4 a4 = g_agg[(size_t)i * 2 + 0];
        float4 a2 = g_agg[(size_t)i * 2 + 1];
        float t[6] = {h4.x + a4.x, h4.y + a4.y, h4.z + a4.z,
                      h4.w + a4.w, h2.x + a2.x, h2.y + a2.y};
#pragma unroll
        for (int j = 0; j < 6; j++) {
            float acc = sb[j];
#pragma unroll
            for (int k = 0; k < 6; k++) acc = fmaf(t[k], sW[k * 6 + j], acc);
            s = fmaf(acc, sWl[j], s);
        }
        c = 1.f;
        g = __ldg(batch + i);
    }

    // Segmented suffix reduction over sorted keys within the warp.
    int lane = threadIdx.x & 31;
#pragma unroll
    for (int off = 1; off < 32; off <<= 1) {
        float ov = __shfl_down_sync(0xFFFFFFFFu, s, off);
        float oc = __shfl_down_sync(0xFFFFFFFFu, c, off);
        int   og = __shfl_down_sync(0xFFFFFFFFu, g, off);
        if (lane + off < 32 && og == g) { s += ov; c += oc; }
    }
    int gprev = __shfl_up_sync(0xFFFFFFFFu, g, 1);
    bool head = (lane == 0) || (gprev != g);
    if (head && g >= 0) {
        atomicAdd(&g_gsum[g], s);
        atomicAdd(&g_gcnt[g], c);
    }
}

// ---------------------------------------------------------------------------
// Finalize: out[g] = gsum[g] / max(cnt, 1) + bl
// ---------------------------------------------------------------------------
__global__ __launch_bounds__(256) void final_kernel(const float* __restrict__ bl,
                                                    float* __restrict__ out, int G) {
    int g = blockIdx.x * 256 + threadIdx.x;
    if (g < G) out[g] = g_gsum[g] / fmaxf(g_gcnt[g], 1.f) + bl[0];
}

// ---------------------------------------------------------------------------
extern "C" void kernel_launch(void* const* d_in, const int* in_sizes, int n_in,
                              void* d_out, int out_size) {
    const float* x     = (const float*)d_in[0];
    const int*   ei    = (const int*)d_in[1];     // int32 (JAX x64 disabled)
    const float* ea    = (const float*)d_in[2];
    const int*   batch = (const int*)d_in[3];     // int32
    const float* W1 = (const float*)d_in[4];
    const float* b1 = (const float*)d_in[5];
    const float* W2 = (const float*)d_in[6];
    const float* b2 = (const float*)d_in[7];
    const float* W3 = (const float*)d_in[8];
    const float* b3 = (const float*)d_in[9];
    const float* Wl = (const float*)d_in[10];
    const float* bl = (const float*)d_in[11];
    float* out = (float*)d_out;

    int N = in_sizes[0] / 6;   // x is [N, 6]
    int E = in_sizes[2] / 6;   // edge_attr is [E, 6]
    int G = out_size;          // out is [G, 1]

    int nb = (N + 255) / 256;
    int eb = (E + 255) / 256;
    int gb = (G + 255) / 256;

    init_kernel<<<nb, 256>>>(x, N, G);

    edge_kernel<<<eb, 256>>>(ei, ea, E);
    node_kernel<<<nb, 256>>>(W1, b1, N);

    edge_kernel<<<eb, 256>>>(ei, ea, E);
    node_kernel<<<nb, 256>>>(W2, b2, N);

    edge_kernel<<<eb, 256>>>(ei, ea, E);
    node3_kernel<<<nb, 256>>>(W3, b3, Wl, batch, N);

    final_kernel<<<gb, 256>>>(bl, out, G);
}

// round 5
// speedup vs baseline: 1.4129x; 1.4129x over previous
#include <cuda_runtime.h>
#include <cuda_fp16.h>
#include <cstdint>

// Problem-size maxima (fixed by the reference generator).
static constexpr int NMAX = 1000000;
static constexpr int GMAX = 1000;

// Node state: 2 float4 per node (row stride 32B, first 6 floats used).
// Aggregation buffer: 8 fp16 per node (16B) -> ONE red.global.add.v4.f16x2
// per edge covers all 6 features (+2 zero pad lanes). uint4 => 16B aligned.
__device__ float4 g_h   [(size_t)NMAX * 2];
__device__ uint4  g_aggh[(size_t)NMAX];
__device__ float  g_gsum[GMAX];
__device__ float  g_gcnt[GMAX];

// ---------------------------------------------------------------------------
// Init: h <- x (padded), agg <- 0, pool accumulators <- 0.
// ---------------------------------------------------------------------------
__global__ __launch_bounds__(256) void init_kernel(const float* __restrict__ x,
                                                   int N, int G) {
    int i = blockIdx.x * 256 + threadIdx.x;
    if (i < N) {
        const float2* xp = reinterpret_cast<const float2*>(x + (size_t)i * 6);
        float2 a = __ldcs(xp + 0);
        float2 b = __ldcs(xp + 1);
        float2 c = __ldcs(xp + 2);
        g_h[(size_t)i * 2 + 0] = make_float4(a.x, a.y, b.x, b.y);
        g_h[(size_t)i * 2 + 1] = make_float4(c.x, c.y, 0.f, 0.f);
        g_aggh[i] = make_uint4(0u, 0u, 0u, 0u);
    }
    if (i < G) { g_gsum[i] = 0.f; g_gcnt[i] = 0.f; }
}

// ---------------------------------------------------------------------------
// Edge pass: m = relu(h[src] + e); agg[dst] += m as ONE 128-bit f16x2
// vector reduction (halves atomic op count vs v4.f32+v2.f32).
// edge_index / edge_attr streamed with .cs so the ~384MB/layer stream
// doesn't evict the 48MB h/agg working set from L2.
// ---------------------------------------------------------------------------
__global__ __launch_bounds__(256) void edge_kernel(const int* __restrict__ ei,
                                                   const float* __restrict__ ea,
                                                   int E) {
    int e = blockIdx.x * 256 + threadIdx.x;
    if (e >= E) return;
    int s = __ldcs(ei + e);
    int d = __ldcs(ei + (size_t)E + e);

    float4 h4 = __ldg(&g_h[(size_t)s * 2 + 0]);
    float4 h2 = __ldg(&g_h[(size_t)s * 2 + 1]);

    const float2* ep = reinterpret_cast<const float2*>(ea + (size_t)e * 6);
    float2 e0 = __ldcs(ep + 0);
    float2 e1 = __ldcs(ep + 1);
    float2 e2 = __ldcs(ep + 2);

    float m0 = fmaxf(h4.x + e0.x, 0.f);
    float m1 = fmaxf(h4.y + e0.y, 0.f);
    float m2 = fmaxf(h4.z + e1.x, 0.f);
    float m3 = fmaxf(h4.w + e1.y, 0.f);
    float m4 = fmaxf(h2.x + e2.x, 0.f);
    float m5 = fmaxf(h2.y + e2.y, 0.f);

    __half2 p01 = __floats2half2_rn(m0, m1);
    __half2 p23 = __floats2half2_rn(m2, m3);
    __half2 p45 = __floats2half2_rn(m4, m5);
    unsigned u01 = *reinterpret_cast<unsigned*>(&p01);
    unsigned u23 = *reinterpret_cast<unsigned*>(&p23);
    unsigned u45 = *reinterpret_cast<unsigned*>(&p45);

    unsigned long long ap =
        (unsigned long long)__cvta_generic_to_global(&g_aggh[d]);
    asm volatile("red.global.add.noftz.v4.f16x2 [%0], {%1,%2,%3,%4};"
                 :: "l"(ap), "r"(u01), "r"(u23), "r"(u45), "r"(0u) : "memory");
}

// ---------------------------------------------------------------------------
// Unpack fp16 agg row to 6 floats.
// ---------------------------------------------------------------------------
__device__ __forceinline__ void load_agg6(int i, float* a) {
    uint4 av = g_aggh[i];
    __half2 a01 = *reinterpret_cast<__half2*>(&av.x);
    __half2 a23 = *reinterpret_cast<__half2*>(&av.y);
    __half2 a45 = *reinterpret_cast<__half2*>(&av.z);
    float2 f01 = __half22float2(a01);
    float2 f23 = __half22float2(a23);
    float2 f45 = __half22float2(a45);
    a[0] = f01.x; a[1] = f01.y; a[2] = f23.x;
    a[3] = f23.y; a[4] = f45.x; a[5] = f45.y;
}

// ---------------------------------------------------------------------------
// Node update: h <- relu((h + agg) @ W + b); agg <- 0 (for next layer).
// ---------------------------------------------------------------------------
__global__ __launch_bounds__(256) void node_kernel(const float* __restrict__ W,
                                                   const float* __restrict__ b,
                                                   int N) {
    __shared__ float sW[36];
    __shared__ float sb[6];
    if (threadIdx.x < 36) sW[threadIdx.x] = W[threadIdx.x];
    if (threadIdx.x < 6)  sb[threadIdx.x] = b[threadIdx.x];
    __syncthreads();

    int i = blockIdx.x * 256 + threadIdx.x;
    if (i >= N) return;

    float4 h4 = g_h[(size_t)i * 2 + 0];
    float4 h2 = g_h[(size_t)i * 2 + 1];
    float a[6];
    load_agg6(i, a);

    float t[6] = {h4.x + a[0], h4.y + a[1], h4.z + a[2],
                  h4.w + a[3], h2.x + a[4], h2.y + a[5]};
    float y[6];
#pragma unroll
    for (int j = 0; j < 6; j++) {
        float acc = sb[j];
#pragma unroll
        for (int k = 0; k < 6; k++) acc = fmaf(t[k], sW[k * 6 + j], acc);
        y[j] = fmaxf(acc, 0.f);
    }

    g_h[(size_t)i * 2 + 0] = make_float4(y[0], y[1], y[2], y[3]);
    g_h[(size_t)i * 2 + 1] = make_float4(y[4], y[5], 0.f, 0.f);
    g_aggh[i] = make_uint4(0u, 0u, 0u, 0u);
}

// ---------------------------------------------------------------------------
// Layer-3 node update fused with pooling head:
//   y = (h + agg) @ W3 + b3 (no relu);  s = y . Wl
//   pooled@Wl = (sum_i s_i)/cnt, so accumulate (s, 1) per graph.
// batch (int32, sorted) -> warp-segmented reduction, ~1 atomic per run.
// ---------------------------------------------------------------------------
__global__ __launch_bounds__(256) void node3_kernel(const float* __restrict__ W,
                                                    const float* __restrict__ b,
                                                    const float* __restrict__ Wl,
                                                    const int* __restrict__ batch,
                                                    int N) {
    __shared__ float sW[36];
    __shared__ float sb[6];
    __shared__ float sWl[6];
    if (threadIdx.x < 36) sW[threadIdx.x] = W[threadIdx.x];
    if (threadIdx.x < 6) { sb[threadIdx.x] = b[threadIdx.x]; sWl[threadIdx.x] = Wl[threadIdx.x]; }
    __syncthreads();

    int i = blockIdx.x * 256 + threadIdx.x;
    float s = 0.f, c = 0.f;
    int g = -1;
    if (i < N) {
        float4 h4 = g_h[(size_t)i * 2 + 0];
        float4 h2 = g_h[(size_t)i * 2 + 1];
        float a[6];
        load_agg6(i, a);
        float t[6] = {h4.x + a[0], h4.y + a[1], h4.z + a[2],
                      h4.w + a[3], h2.x + a[4], h2.y + a[5]};
#pragma unroll
        for (int j = 0; j < 6; j++) {
            float acc = sb[j];
#pragma unroll
            for (int k = 0; k < 6; k++) acc = fmaf(t[k], sW[k * 6 + j], acc);
            s = fmaf(acc, sWl[j], s);
        }
        c = 1.f;
        g = __ldg(batch + i);
    }

    // Segmented suffix reduction over sorted keys within the warp.
    int lane = threadIdx.x & 31;
#pragma unroll
    for (int off = 1; off < 32; off <<= 1) {
        float ov = __shfl_down_sync(0xFFFFFFFFu, s, off);
        float oc = __shfl_down_sync(0xFFFFFFFFu, c, off);
        int   og = __shfl_down_sync(0xFFFFFFFFu, g, off);
        if (lane + off < 32 && og == g) { s += ov; c += oc; }
    }
    int gprev = __shfl_up_sync(0xFFFFFFFFu, g, 1);
    bool head = (lane == 0) || (gprev != g);
    if (head && g >= 0) {
        atomicAdd(&g_gsum[g], s);
        atomicAdd(&g_gcnt[g], c);
    }
}

// ---------------------------------------------------------------------------
// Finalize: out[g] = gsum[g] / max(cnt, 1) + bl
// ---------------------------------------------------------------------------
__global__ __launch_bounds__(256) void final_kernel(const float* __restrict__ bl,
                                                    float* __restrict__ out, int G) {
    int g = blockIdx.x * 256 + threadIdx.x;
    if (g < G) out[g] = g_gsum[g] / fmaxf(g_gcnt[g], 1.f) + bl[0];
}

// ---------------------------------------------------------------------------
extern "C" void kernel_launch(void* const* d_in, const int* in_sizes, int n_in,
                              void* d_out, int out_size) {
    const float* x     = (const float*)d_in[0];
    const int*   ei    = (const int*)d_in[1];     // int32 (JAX x64 disabled)
    const float* ea    = (const float*)d_in[2];
    const int*   batch = (const int*)d_in[3];     // int32
    const float* W1 = (const float*)d_in[4];
    const float* b1 = (const float*)d_in[5];
    const float* W2 = (const float*)d_in[6];
    const float* b2 = (const float*)d_in[7];
    const float* W3 = (const float*)d_in[8];
    const float* b3 = (const float*)d_in[9];
    const float* Wl = (const float*)d_in[10];
    const float* bl = (const float*)d_in[11];
    float* out = (float*)d_out;

    int N = in_sizes[0] / 6;   // x is [N, 6]
    int E = in_sizes[2] / 6;   // edge_attr is [E, 6]
    int G = out_size;          // out is [G, 1]

    int nb = (N + 255) / 256;
    int eb = (E + 255) / 256;
    int gb = (G + 255) / 256;

    init_kernel<<<nb, 256>>>(x, N, G);

    edge_kernel<<<eb, 256>>>(ei, ea, E);
    node_kernel<<<nb, 256>>>(W1, b1, N);

    edge_kernel<<<eb, 256>>>(ei, ea, E);
    node_kernel<<<nb, 256>>>(W2, b2, N);

    edge_kernel<<<eb, 256>>>(ei, ea, E);
    node3_kernel<<<nb, 256>>>(W3, b3, Wl, batch, N);

    final_kernel<<<gb, 256>>>(bl, out, G);
}

// round 6
// speedup vs baseline: 1.6685x; 1.1809x over previous
#include <cuda_runtime.h>
#include <cuda_fp16.h>
#include <cstdint>

// Problem-size maxima (fixed by the reference generator).
static constexpr int NMAX = 1000000;
static constexpr int GMAX = 1000;

// Node state AND aggregation buffer both packed as 8 fp16 (16B/row):
//  - h gather in edge pass = ONE divergent LDG.128 (was two)
//  - agg scatter = ONE red.global.add.v4.f16x2
// uint4 guarantees 16B alignment.
__device__ uint4 g_h  [(size_t)NMAX];
__device__ uint4 g_agg[(size_t)NMAX];
__device__ float g_gsum[GMAX];
__device__ float g_gcnt[GMAX];

__device__ __forceinline__ uint4 pack6(float v0, float v1, float v2,
                                       float v3, float v4, float v5) {
    __half2 p01 = __floats2half2_rn(v0, v1);
    __half2 p23 = __floats2half2_rn(v2, v3);
    __half2 p45 = __floats2half2_rn(v4, v5);
    uint4 r;
    r.x = *reinterpret_cast<unsigned*>(&p01);
    r.y = *reinterpret_cast<unsigned*>(&p23);
    r.z = *reinterpret_cast<unsigned*>(&p45);
    r.w = 0u;
    return r;
}

__device__ __forceinline__ void unpack6(uint4 v, float* a) {
    float2 f01 = __half22float2(*reinterpret_cast<__half2*>(&v.x));
    float2 f23 = __half22float2(*reinterpret_cast<__half2*>(&v.y));
    float2 f45 = __half22float2(*reinterpret_cast<__half2*>(&v.z));
    a[0] = f01.x; a[1] = f01.y; a[2] = f23.x;
    a[3] = f23.y; a[4] = f45.x; a[5] = f45.y;
}

// ---------------------------------------------------------------------------
// Init: h <- fp16(x), agg <- 0, pool accumulators <- 0.
// ---------------------------------------------------------------------------
__global__ __launch_bounds__(256) void init_kernel(const float* __restrict__ x,
                                                   int N, int G) {
    int i = blockIdx.x * 256 + threadIdx.x;
    if (i < N) {
        const float2* xp = reinterpret_cast<const float2*>(x + (size_t)i * 6);
        float2 a = __ldcs(xp + 0);
        float2 b = __ldcs(xp + 1);
        float2 c = __ldcs(xp + 2);
        g_h[i]   = pack6(a.x, a.y, b.x, b.y, c.x, c.y);
        g_agg[i] = make_uint4(0u, 0u, 0u, 0u);
    }
    if (i < G) { g_gsum[i] = 0.f; g_gcnt[i] = 0.f; }
}

// ---------------------------------------------------------------------------
// Edge pass: m = relu(h[src] + e); agg[dst] += fp16(m).
// One divergent LDG.128 gather + one 128-bit f16x2 vector reduction per edge.
// Message math in fp32 (single rounding at the reduction).
// ---------------------------------------------------------------------------
__global__ __launch_bounds__(256) void edge_kernel(const int* __restrict__ ei,
                                                   const float* __restrict__ ea,
                                                   int E) {
    int e = blockIdx.x * 256 + threadIdx.x;
    if (e >= E) return;
    int s = __ldcs(ei + e);
    int d = __ldcs(ei + (size_t)E + e);

    uint4 hv = __ldg(&g_h[s]);
    float h[6];
    unpack6(hv, h);

    const float2* ep = reinterpret_cast<const float2*>(ea + (size_t)e * 6);
    float2 e0 = __ldcs(ep + 0);
    float2 e1 = __ldcs(ep + 1);
    float2 e2 = __ldcs(ep + 2);

    float m0 = fmaxf(h[0] + e0.x, 0.f);
    float m1 = fmaxf(h[1] + e0.y, 0.f);
    float m2 = fmaxf(h[2] + e1.x, 0.f);
    float m3 = fmaxf(h[3] + e1.y, 0.f);
    float m4 = fmaxf(h[4] + e2.x, 0.f);
    float m5 = fmaxf(h[5] + e2.y, 0.f);

    uint4 m = pack6(m0, m1, m2, m3, m4, m5);
    unsigned long long ap =
        (unsigned long long)__cvta_generic_to_global(&g_agg[d]);
    asm volatile("red.global.add.noftz.v4.f16x2 [%0], {%1,%2,%3,%4};"
                 :: "l"(ap), "r"(m.x), "r"(m.y), "r"(m.z), "r"(0u) : "memory");
}

// ---------------------------------------------------------------------------
// Node update: h <- fp16(relu((h + agg) @ W + b)); agg <- 0.
// ---------------------------------------------------------------------------
__global__ __launch_bounds__(256) void node_kernel(const float* __restrict__ W,
                                                   const float* __restrict__ b,
                                                   int N) {
    __shared__ float sW[36];
    __shared__ float sb[6];
    if (threadIdx.x < 36) sW[threadIdx.x] = W[threadIdx.x];
    if (threadIdx.x < 6)  sb[threadIdx.x] = b[threadIdx.x];
    __syncthreads();

    int i = blockIdx.x * 256 + threadIdx.x;
    if (i >= N) return;

    float h[6], a[6];
    unpack6(g_h[i], h);
    unpack6(g_agg[i], a);

    float t[6] = {h[0] + a[0], h[1] + a[1], h[2] + a[2],
                  h[3] + a[3], h[4] + a[4], h[5] + a[5]};
    float y[6];
#pragma unroll
    for (int j = 0; j < 6; j++) {
        float acc = sb[j];
#pragma unroll
        for (int k = 0; k < 6; k++) acc = fmaf(t[k], sW[k * 6 + j], acc);
        y[j] = fmaxf(acc, 0.f);
    }

    g_h[i]   = pack6(y[0], y[1], y[2], y[3], y[4], y[5]);
    g_agg[i] = make_uint4(0u, 0u, 0u, 0u);
}

// ---------------------------------------------------------------------------
// Layer-3 node update fused with pooling head:
//   y = (h + agg) @ W3 + b3 (no relu);  s = y . Wl
//   pooled@Wl = (sum_i s_i)/cnt  -> accumulate (s, 1) per graph.
// batch (int32, sorted) -> warp-segmented reduction, ~1 atomic per run.
// ---------------------------------------------------------------------------
__global__ __launch_bounds__(256) void node3_kernel(const float* __restrict__ W,
                                                    const float* __restrict__ b,
                                                    const float* __restrict__ Wl,
                                                    const int* __restrict__ batch,
                                                    int N) {
    __shared__ float sW[36];
    __shared__ float sb[6];
    __shared__ float sWl[6];
    if (threadIdx.x < 36) sW[threadIdx.x] = W[threadIdx.x];
    if (threadIdx.x < 6) { sb[threadIdx.x] = b[threadIdx.x]; sWl[threadIdx.x] = Wl[threadIdx.x]; }
    __syncthreads();

    int i = blockIdx.x * 256 + threadIdx.x;
    float s = 0.f, c = 0.f;
    int g = -1;
    if (i < N) {
        float h[6], a[6];
        unpack6(g_h[i], h);
        unpack6(g_agg[i], a);
        float t[6] = {h[0] + a[0], h[1] + a[1], h[2] + a[2],
                      h[3] + a[3], h[4] + a[4], h[5] + a[5]};
#pragma unroll
        for (int j = 0; j < 6; j++) {
            float acc = sb[j];
#pragma unroll
            for (int k = 0; k < 6; k++) acc = fmaf(t[k], sW[k * 6 + j], acc);
            s = fmaf(acc, sWl[j], s);
        }
        c = 1.f;
        g = __ldg(batch + i);
    }

    // Segmented suffix reduction over sorted keys within the warp.
    int lane = threadIdx.x & 31;
#pragma unroll
    for (int off = 1; off < 32; off <<= 1) {
        float ov = __shfl_down_sync(0xFFFFFFFFu, s, off);
        float oc = __shfl_down_sync(0xFFFFFFFFu, c, off);
        int   og = __shfl_down_sync(0xFFFFFFFFu, g, off);
        if (lane + off < 32 && og == g) { s += ov; c += oc; }
    }
    int gprev = __shfl_up_sync(0xFFFFFFFFu, g, 1);
    bool head = (lane == 0) || (gprev != g);
    if (head && g >= 0) {
        atomicAdd(&g_gsum[g], s);
        atomicAdd(&g_gcnt[g], c);
    }
}

// ---------------------------------------------------------------------------
// Finalize: out[g] = gsum[g] / max(cnt, 1) + bl
// ---------------------------------------------------------------------------
__global__ __launch_bounds__(256) void final_kernel(const float* __restrict__ bl,
                                                    float* __restrict__ out, int G) {
    int g = blockIdx.x * 256 + threadIdx.x;
    if (g < G) out[g] = g_gsum[g] / fmaxf(g_gcnt[g], 1.f) + bl[0];
}

// ---------------------------------------------------------------------------
extern "C" void kernel_launch(void* const* d_in, const int* in_sizes, int n_in,
                              void* d_out, int out_size) {
    const float* x     = (const float*)d_in[0];
    const int*   ei    = (const int*)d_in[1];     // int32 (JAX x64 disabled)
    const float* ea    = (const float*)d_in[2];
    const int*   batch = (const int*)d_in[3];     // int32
    const float* W1 = (const float*)d_in[4];
    const float* b1 = (const float*)d_in[5];
    const float* W2 = (const float*)d_in[6];
    const float* b2 = (const float*)d_in[7];
    const float* W3 = (const float*)d_in[8];
    const float* b3 = (const float*)d_in[9];
    const float* Wl = (const float*)d_in[10];
    const float* bl = (const float*)d_in[11];
    float* out = (float*)d_out;

    int N = in_sizes[0] / 6;   // x is [N, 6]
    int E = in_sizes[2] / 6;   // edge_attr is [E, 6]
    int G = out_size;          // out is [G, 1]

    int nb = (N + 255) / 256;
    int eb = (E + 255) / 256;
    int gb = (G + 255) / 256;

    init_kernel<<<nb, 256>>>(x, N, G);

    edge_kernel<<<eb, 256>>>(ei, ea, E);
    node_kernel<<<nb, 256>>>(W1, b1, N);

    edge_kernel<<<eb, 256>>>(ei, ea, E);
    node_kernel<<<nb, 256>>>(W2, b2, N);

    edge_kernel<<<eb, 256>>>(ei, ea, E);
    node3_kernel<<<nb, 256>>>(W3, b3, Wl, batch, N);

    final_kernel<<<gb, 256>>>(bl, out, G);
}